// round 12
// baseline (speedup 1.0000x reference)
#include <cuda_runtime.h>
#include <cuda_bf16.h>
#include <stdint.h>

// Problem constants (fixed by the dataset)
#define NN 100000      // nodes
#define NE 1600000     // edges
#define NF 256         // input features
#define NH 128         // hidden
#define NC 40          // classes

// ---------------- Scratch (static __device__, no allocations) ----------------
__device__ float g_h1[(size_t)NN * NH];   // GEMM output / agg input
__device__ float g_ha[(size_t)NN * NH];   // agg output / next GEMM input
__device__ int   g_csr[NE];               // CSR src list grouped by dst
__device__ int   g_deg[NN];
__device__ int   g_off[NN];
__device__ int   g_cur[NN];
__device__ float g_dinv[NN];
__device__ int   g_bsum[128];
__device__ int   g_boff[128];
__device__ int   g_e64;                   // 1 if edge_index is int64, 0 if int32

__device__ __forceinline__ float* scratch_buf(int sel) {
    return (sel == 0) ? g_h1 : g_ha;
}

// Edge load honoring detected dtype.
__device__ __forceinline__ int load_edge(const void* ei, long long idx) {
    if (g_e64) return (int)((const long long*)ei)[idx];
    return ((const int*)ei)[idx];
}

// Packed f32x2 helpers (Blackwell base ISA)
#define FMA_F32X2(d, a, b) \
    asm("fma.rn.f32x2 %0, %1, %2, %3;" : "=l"(d) : "l"(a), "l"(b), "l"(d))
#define PACK_DUP(out, x) \
    asm("mov.b64 %0, {%1, %1};" : "=l"(out) : "f"(x))
#define UNPACK2(lo, hi, in) \
    asm("mov.b64 {%0, %1}, %2;" : "=f"(lo), "=f"(hi) : "l"(in))

// cp.async helpers (sm_80+ base ISA)
#define CP_ASYNC16(dst_smem_u32, src_gen) \
    asm volatile("cp.async.cg.shared.global [%0], [%1], 16;" \
                 :: "r"(dst_smem_u32), "l"(src_gen))
#define CP_COMMIT() asm volatile("cp.async.commit_group;" ::: "memory")
#define CP_WAIT1()  asm volatile("cp.async.wait_group 1;" ::: "memory")
#define CP_WAIT0()  asm volatile("cp.async.wait_group 0;" ::: "memory")

__device__ __forceinline__ uint32_t smem_addr(const void* p) {
    return (uint32_t)__cvta_generic_to_shared(p);
}

// ---------------- dtype probe ----------------
// JAX silently downgrades int64->int32 when x64 is disabled (the default).
__global__ void k_detect_dtype(const long long* __restrict__ ei) {
    __shared__ int ok64;
    if (threadIdx.x == 0) ok64 = 1;
    __syncthreads();
    for (int i = threadIdx.x; i < 2048; i += blockDim.x) {
        long long v = ei[i];
        if (v < 0 || v >= (long long)NN) ok64 = 0;
    }
    __syncthreads();
    if (threadIdx.x == 0) g_e64 = ok64;
}

// ---------------- Degree + CSR build ----------------
__global__ void k_zero_deg(int n) {
    int gid = blockIdx.x * blockDim.x + threadIdx.x;
    if (gid < n) g_deg[gid] = 0;
}

__global__ void k_count_deg(const void* __restrict__ ei, int E) {
    int e = blockIdx.x * blockDim.x + threadIdx.x;
    if (e < E) {
        int d = load_edge(ei, (long long)E + e);
        if (d >= 0 && d < NN) atomicAdd(&g_deg[d], 1);
    }
}

__global__ void k_scan_blocks(int n) {
    int tid = threadIdx.x;
    int gid = blockIdx.x * 1024 + tid;
    int lane = tid & 31, wid = tid >> 5;
    int v = (gid < n) ? g_deg[gid] : 0;
    int x = v;
#pragma unroll
    for (int d = 1; d < 32; d <<= 1) {
        int y = __shfl_up_sync(0xffffffffu, x, d);
        if (lane >= d) x += y;
    }
    __shared__ int ws[32];
    if (lane == 31) ws[wid] = x;
    __syncthreads();
    if (wid == 0) {
        int w = ws[lane];
        int t = w;
#pragma unroll
        for (int d = 1; d < 32; d <<= 1) {
            int y = __shfl_up_sync(0xffffffffu, t, d);
            if (lane >= d) t += y;
        }
        ws[lane] = t - w;
    }
    __syncthreads();
    int excl = ws[wid] + x - v;
    if (gid < n) {
        g_off[gid] = excl;
        g_dinv[gid] = rsqrtf((float)v + 1.0f);
    }
    if (tid == 1023) g_bsum[blockIdx.x] = excl + v;
}

__global__ void k_scan_sums(int nb) {
    int tid = threadIdx.x, lane = tid & 31, wid = tid >> 5;
    int v = (tid < nb) ? g_bsum[tid] : 0;
    int x = v;
#pragma unroll
    for (int d = 1; d < 32; d <<= 1) {
        int y = __shfl_up_sync(0xffffffffu, x, d);
        if (lane >= d) x += y;
    }
    __shared__ int ws[4];
    if (lane == 31) ws[wid] = x;
    __syncthreads();
    if (tid == 0) {
        int a = 0;
#pragma unroll
        for (int i = 0; i < 4; i++) { int t = ws[i]; ws[i] = a; a += t; }
    }
    __syncthreads();
    int excl = ws[wid] + x - v;
    if (tid < nb) g_boff[tid] = excl;
}

__global__ void k_scan_add(int n) {
    int gid = blockIdx.x * 1024 + threadIdx.x;
    if (gid < n) {
        int o = g_off[gid] + g_boff[blockIdx.x];
        g_off[gid] = o;
        g_cur[gid] = o;
    }
}

__global__ void k_fill_csr(const void* __restrict__ ei, int E) {
    int e = blockIdx.x * blockDim.x + threadIdx.x;
    if (e < E) {
        int s = load_edge(ei, e);
        int d = load_edge(ei, (long long)E + e);
        if (s >= 0 && s < NN && d >= 0 && d < NN) {
            int p = atomicAdd(&g_cur[d], 1);
            g_csr[p] = s;
        }
    }
}

// ------- f32x2 SGEMM (layers 1-2), cp.async double-buffered ------------------
// C[M,128] = dinv[row] * (A[M,K] @ B[K,128])
// BM=128, BN=128, BK=16, TM=8, TN=8, 256 threads.
// A staged row-major (stride 20 floats, 16B-aligned rows, warp-broadcast reads).
#define G2_BM 128
#define G2_BK 16
#define G2_ASTRIDE 20                       // floats per A smem row (16 + 4 pad)
#define G2_ASTAGE (G2_BM * G2_ASTRIDE)      // floats per A stage
#define G2_BSTAGE (G2_BK * 128)             // floats per B stage

template <int K>
__global__ void __launch_bounds__(256)
sgemm2(const float* __restrict__ Aext, int asel,
       const float* __restrict__ B, int csel, int M) {
    constexpr int TM = 8, TN = 8;
    constexpr int NCHUNK = K / G2_BK;

    const float* A = (asel < 0) ? Aext : scratch_buf(asel);
    float* C = scratch_buf(csel);

    __shared__ __align__(16) float As[2][G2_ASTAGE];
    __shared__ __align__(16) float Bs[2][G2_BSTAGE];

    const int block_row = blockIdx.y * G2_BM;
    const int tid = threadIdx.x;
    const int tcol = tid & 15;          // 0..15
    const int trow = tid >> 4;          // 0..15

    // Per-thread load assignments (2 x 16B for A, 2 x 16B for B per chunk)
    // A: 128 rows x 64B  -> 512 chunks of 16B
    // B: 16 rows x 512B  -> 512 chunks of 16B
    unsigned long long acc[TM][TN / 2];
#pragma unroll
    for (int i = 0; i < TM; i++)
#pragma unroll
        for (int j = 0; j < TN / 2; j++) acc[i][j] = 0ull;

    auto issue_loads = [&](int ch, int buf) {
#pragma unroll
        for (int t = 0; t < 2; t++) {
            int idx = tid + t * 256;            // 0..511
            int r = idx >> 2;                   // A row 0..127
            int seg = idx & 3;                  // 16B segment
            float* dstp = &As[buf][r * G2_ASTRIDE + seg * 4];
            int grow = block_row + r;
            if (grow < M) {
                CP_ASYNC16(smem_addr(dstp),
                           A + (size_t)grow * K + ch * G2_BK + seg * 4);
            } else {
                *(float4*)dstp = make_float4(0.f, 0.f, 0.f, 0.f);
            }
        }
#pragma unroll
        for (int t = 0; t < 2; t++) {
            int idx = tid + t * 256;            // 0..511
            int r = idx >> 5;                   // B row 0..15
            int seg = idx & 31;                 // 16B segment
            float* dstp = &Bs[buf][r * 128 + seg * 4];
            CP_ASYNC16(smem_addr(dstp),
                       B + (size_t)(ch * G2_BK + r) * 128 + seg * 4);
        }
        CP_COMMIT();
    };

    issue_loads(0, 0);

#pragma unroll 1
    for (int ch = 0; ch < NCHUNK; ch++) {
        const int buf = ch & 1;
        if (ch + 1 < NCHUNK) {
            issue_loads(ch + 1, buf ^ 1);
            CP_WAIT1();
        } else {
            CP_WAIT0();
        }
        __syncthreads();

        const float* __restrict__ as = As[buf];
        const float* __restrict__ bs = Bs[buf];
#pragma unroll
        for (int k = 0; k < G2_BK; k++) {
            unsigned long long a2[TM], b2[TN / 2];
#pragma unroll
            for (int i = 0; i < TM; i++) {
                float ra = as[(trow * TM + i) * G2_ASTRIDE + k];
                PACK_DUP(a2[i], ra);
            }
#pragma unroll
            for (int j = 0; j < TN / 2; j++)
                b2[j] = *(const unsigned long long*)&bs[k * 128 + tcol * TN + 2 * j];
#pragma unroll
            for (int i = 0; i < TM; i++)
#pragma unroll
                for (int j = 0; j < TN / 2; j++)
                    FMA_F32X2(acc[i][j], a2[i], b2[j]);
        }
        __syncthreads();
    }

    // Epilogue: scale by dinv[row], store
#pragma unroll
    for (int i = 0; i < TM; i++) {
        int row = block_row + trow * TM + i;
        if (row < M) {
            float scale = g_dinv[row];
            float* crow = C + (size_t)row * NH + tcol * TN;
#pragma unroll
            for (int j = 0; j < TN / 2; j += 2) {
                float4 v;
                UNPACK2(v.x, v.y, acc[i][j]);
                UNPACK2(v.z, v.w, acc[i][j + 1]);
                v.x *= scale; v.y *= scale; v.z *= scale; v.w *= scale;
                *(float4*)(crow + 2 * j) = v;
            }
        }
    }
}

// ---------------- f32x2 classifier: out[M,40] = A[M,128] @ Wc + bc -----------
// BM=128, BN=40, BK=32, TM=4, TN=8 -> 160 threads.
__global__ void __launch_bounds__(160)
sgemm_cls(int asel, const float* __restrict__ B,
          float* __restrict__ C, const float* __restrict__ bias, int M) {
    constexpr int BM = 128, BN = 40, BK = 32, TM = 4, TN = 8;
    constexpr int THREADS = 160;
    constexpr int K = NH;

    const float* A = scratch_buf(asel);

    __shared__ __align__(16) float As[BK][BM + 2];
    __shared__ __align__(16) float Bs[BK][BN];

    const int block_row = blockIdx.y * BM;
    const int tid = threadIdx.x;
    const int tcol = tid % (BN / TN);   // 0..4
    const int trow = tid / (BN / TN);   // 0..31

    unsigned long long acc[TM][TN / 2];
#pragma unroll
    for (int i = 0; i < TM; i++)
#pragma unroll
        for (int j = 0; j < TN / 2; j++) acc[i][j] = 0ull;

    for (int k0 = 0; k0 < K; k0 += BK) {
        for (int i = tid * 4; i < BM * BK; i += THREADS * 4) {
            int r = i / BK, c = i % BK;
            int row = block_row + r;
            float4 v = make_float4(0.f, 0.f, 0.f, 0.f);
            if (row < M) v = *(const float4*)(A + (size_t)row * K + k0 + c);
            As[c + 0][r] = v.x;
            As[c + 1][r] = v.y;
            As[c + 2][r] = v.z;
            As[c + 3][r] = v.w;
        }
        for (int i = tid * 4; i < BK * BN; i += THREADS * 4) {
            int r = i / BN, c = i % BN;
            *(float4*)&Bs[r][c] = *(const float4*)(B + (size_t)(k0 + r) * BN + c);
        }
        __syncthreads();

#pragma unroll
        for (int k = 0; k < BK; k++) {
            unsigned long long a2[TM], b2[TN / 2];
#pragma unroll
            for (int i = 0; i < TM; i++) {
                float ra = As[k][trow * TM + i];
                PACK_DUP(a2[i], ra);
            }
#pragma unroll
            for (int j = 0; j < TN / 2; j++)
                b2[j] = *(const unsigned long long*)&Bs[k][tcol * TN + 2 * j];
#pragma unroll
            for (int i = 0; i < TM; i++)
#pragma unroll
                for (int j = 0; j < TN / 2; j++)
                    FMA_F32X2(acc[i][j], a2[i], b2[j]);
        }
        __syncthreads();
    }

#pragma unroll
    for (int i = 0; i < TM; i++) {
        int row = block_row + trow * TM + i;
        if (row < M) {
            float* crow = C + (size_t)row * NC + tcol * TN;
#pragma unroll
            for (int j = 0; j < TN / 2; j++) {
                float lo, hi;
                UNPACK2(lo, hi, acc[i][j]);
                crow[2 * j + 0] = lo + bias[tcol * TN + 2 * j + 0];
                crow[2 * j + 1] = hi + bias[tcol * TN + 2 * j + 1];
            }
        }
    }
}

// ---------------- Fused aggregation: warp per node ----------------
// Input h is PRE-SCALED: hn[i] = dinv[i] * (X@W)[i].
// out[i] = relu( dinv[i] * ( hn[i] + sum_{j in N(i)} hn[j] ) + bias )
__global__ void k_aggregate(int hsel, const float* __restrict__ bias,
                            int osel, int n_nodes) {
    const float* __restrict__ h = scratch_buf(hsel);
    float* __restrict__ out = scratch_buf(osel);

    int warp = (blockIdx.x * blockDim.x + threadIdx.x) >> 5;
    if (warp >= n_nodes) return;
    int lane = threadIdx.x & 31;
    int node = warp;

    float dd = g_dinv[node];
    int start = g_off[node];
    int cnt = g_deg[node];

    const float* hb = h + (size_t)lane * 4;

    float4 acc = *(const float4*)(hb + (size_t)node * NH);

    int j = 0;
    for (; j + 4 <= cnt; j += 4) {
        int s0 = g_csr[start + j + 0];
        int s1 = g_csr[start + j + 1];
        int s2 = g_csr[start + j + 2];
        int s3 = g_csr[start + j + 3];
        float4 v0 = *(const float4*)(hb + (size_t)s0 * NH);
        float4 v1 = *(const float4*)(hb + (size_t)s1 * NH);
        float4 v2 = *(const float4*)(hb + (size_t)s2 * NH);
        float4 v3 = *(const float4*)(hb + (size_t)s3 * NH);
        acc.x += (v0.x + v1.x) + (v2.x + v3.x);
        acc.y += (v0.y + v1.y) + (v2.y + v3.y);
        acc.z += (v0.z + v1.z) + (v2.z + v3.z);
        acc.w += (v0.w + v1.w) + (v2.w + v3.w);
    }
    for (; j < cnt; j++) {
        int s = g_csr[start + j];
        float4 v = *(const float4*)(hb + (size_t)s * NH);
        acc.x += v.x; acc.y += v.y; acc.z += v.z; acc.w += v.w;
    }

    int c = lane * 4;
    acc.x = fmaxf(fmaf(acc.x, dd, bias[c + 0]), 0.0f);
    acc.y = fmaxf(fmaf(acc.y, dd, bias[c + 1]), 0.0f);
    acc.z = fmaxf(fmaf(acc.z, dd, bias[c + 2]), 0.0f);
    acc.w = fmaxf(fmaf(acc.w, dd, bias[c + 3]), 0.0f);
    *(float4*)(out + (size_t)node * NH + c) = acc;
}

// ---------------- Launch ----------------
extern "C" void kernel_launch(void* const* d_in, const int* in_sizes, int n_in,
                              void* d_out, int out_size) {
    const float* x       = (const float*)d_in[0];
    const void*  ei      = d_in[1];
    const float* W1      = (const float*)d_in[2];
    const float* b1      = (const float*)d_in[3];
    const float* W2      = (const float*)d_in[4];
    const float* b2      = (const float*)d_in[5];
    const float* Wc      = (const float*)d_in[6];
    const float* bc      = (const float*)d_in[7];
    float* out           = (float*)d_out;

    const int N = in_sizes[0] / NF;       // 100000
    const int E = in_sizes[1] / 2;        // 1600000
    const int nb = (N + 1023) / 1024;

    // CSR build (produces g_dinv needed by GEMM epilogues)
    k_detect_dtype<<<1, 256>>>((const long long*)ei);
    k_zero_deg<<<(N + 1023) / 1024, 1024>>>(N);
    k_count_deg<<<(E + 511) / 512, 512>>>(ei, E);
    k_scan_blocks<<<nb, 1024>>>(N);
    k_scan_sums<<<1, 128>>>(nb);
    k_scan_add<<<nb, 1024>>>(N);
    k_fill_csr<<<(E + 511) / 512, 512>>>(ei, E);

    const int agg_blocks = (int)(((long long)N * 32 + 255) / 256);

    // Layer 1: g_h1 = dinv * (x @ W1) ; aggregate -> g_ha
    {
        dim3 grid(1, (N + 127) / 128);
        sgemm2<NF><<<grid, 256>>>(x, -1, W1, 0, N);
    }
    k_aggregate<<<agg_blocks, 256>>>(0, b1, 1, N);

    // Layer 2: g_h1 = dinv * (g_ha @ W2) ; aggregate -> g_ha
    {
        dim3 grid(1, (N + 127) / 128);
        sgemm2<NH><<<grid, 256>>>(nullptr, 1, W2, 0, N);
    }
    k_aggregate<<<agg_blocks, 256>>>(0, b2, 1, N);

    // Classifier: out = g_ha @ Wc + bc   (f32x2)
    {
        dim3 grid(1, (N + 127) / 128);
        sgemm_cls<<<grid, 160>>>(1, Wc, out, bc, N);
    }
}

// round 14
// speedup vs baseline: 1.1238x; 1.1238x over previous
#include <cuda_runtime.h>
#include <cuda_bf16.h>
#include <stdint.h>

// Problem constants (fixed by the dataset)
#define NN 100000      // nodes
#define NE 1600000     // edges
#define NF 256         // input features
#define NH 128         // hidden
#define NC 40          // classes

// ---------------- Scratch (static __device__, no allocations) ----------------
__device__ float g_h1[(size_t)NN * NH];   // GEMM output / agg input
__device__ float g_ha[(size_t)NN * NH];   // agg output / next GEMM input
__device__ int   g_csr[NE];               // CSR src list grouped by dst
__device__ int   g_deg[NN];
__device__ int   g_off[NN];
__device__ int   g_cur[NN];
__device__ float g_dinv[NN];
__device__ int   g_bsum[128];
__device__ int   g_boff[128];
__device__ int   g_e64;                   // 1 if edge_index is int64, 0 if int32

__device__ __forceinline__ float* scratch_buf(int sel) {
    return (sel == 0) ? g_h1 : g_ha;
}

// Edge load honoring detected dtype.
__device__ __forceinline__ int load_edge(const void* ei, long long idx) {
    if (g_e64) return (int)((const long long*)ei)[idx];
    return ((const int*)ei)[idx];
}

// Packed f32x2 helpers (Blackwell base ISA)
#define FMA_F32X2(d, a, b) \
    asm("fma.rn.f32x2 %0, %1, %2, %3;" : "=l"(d) : "l"(a), "l"(b), "l"(d))
#define PACK_DUP(out, x) \
    asm("mov.b64 %0, {%1, %1};" : "=l"(out) : "f"(x))
#define UNPACK2(lo, hi, in) \
    asm("mov.b64 {%0, %1}, %2;" : "=f"(lo), "=f"(hi) : "l"(in))

// ---------------- dtype probe ----------------
// JAX silently downgrades int64->int32 when x64 is disabled (the default).
__global__ void k_detect_dtype(const long long* __restrict__ ei) {
    __shared__ int ok64;
    if (threadIdx.x == 0) ok64 = 1;
    __syncthreads();
    for (int i = threadIdx.x; i < 2048; i += blockDim.x) {
        long long v = ei[i];
        if (v < 0 || v >= (long long)NN) ok64 = 0;
    }
    __syncthreads();
    if (threadIdx.x == 0) g_e64 = ok64;
}

// ---------------- Degree + CSR build ----------------
__global__ void k_zero_deg(int n) {
    int gid = blockIdx.x * blockDim.x + threadIdx.x;
    if (gid < n) g_deg[gid] = 0;
}

__global__ void k_count_deg(const void* __restrict__ ei, int E) {
    int e = blockIdx.x * blockDim.x + threadIdx.x;
    if (e < E) {
        int d = load_edge(ei, (long long)E + e);
        if (d >= 0 && d < NN) atomicAdd(&g_deg[d], 1);
    }
}

__global__ void k_scan_blocks(int n) {
    int tid = threadIdx.x;
    int gid = blockIdx.x * 1024 + tid;
    int lane = tid & 31, wid = tid >> 5;
    int v = (gid < n) ? g_deg[gid] : 0;
    int x = v;
#pragma unroll
    for (int d = 1; d < 32; d <<= 1) {
        int y = __shfl_up_sync(0xffffffffu, x, d);
        if (lane >= d) x += y;
    }
    __shared__ int ws[32];
    if (lane == 31) ws[wid] = x;
    __syncthreads();
    if (wid == 0) {
        int w = ws[lane];
        int t = w;
#pragma unroll
        for (int d = 1; d < 32; d <<= 1) {
            int y = __shfl_up_sync(0xffffffffu, t, d);
            if (lane >= d) t += y;
        }
        ws[lane] = t - w;
    }
    __syncthreads();
    int excl = ws[wid] + x - v;
    if (gid < n) {
        g_off[gid] = excl;
        g_dinv[gid] = rsqrtf((float)v + 1.0f);
    }
    if (tid == 1023) g_bsum[blockIdx.x] = excl + v;
}

__global__ void k_scan_sums(int nb) {
    int tid = threadIdx.x, lane = tid & 31, wid = tid >> 5;
    int v = (tid < nb) ? g_bsum[tid] : 0;
    int x = v;
#pragma unroll
    for (int d = 1; d < 32; d <<= 1) {
        int y = __shfl_up_sync(0xffffffffu, x, d);
        if (lane >= d) x += y;
    }
    __shared__ int ws[4];
    if (lane == 31) ws[wid] = x;
    __syncthreads();
    if (tid == 0) {
        int a = 0;
#pragma unroll
        for (int i = 0; i < 4; i++) { int t = ws[i]; ws[i] = a; a += t; }
    }
    __syncthreads();
    int excl = ws[wid] + x - v;
    if (tid < nb) g_boff[tid] = excl;
}

__global__ void k_scan_add(int n) {
    int gid = blockIdx.x * 1024 + threadIdx.x;
    if (gid < n) {
        int o = g_off[gid] + g_boff[blockIdx.x];
        g_off[gid] = o;
        g_cur[gid] = o;
    }
}

__global__ void k_fill_csr(const void* __restrict__ ei, int E) {
    int e = blockIdx.x * blockDim.x + threadIdx.x;
    if (e < E) {
        int s = load_edge(ei, e);
        int d = load_edge(ei, (long long)E + e);
        if (s >= 0 && s < NN && d >= 0 && d < NN) {
            int p = atomicAdd(&g_cur[d], 1);
            g_csr[p] = s;
        }
    }
}

// ------- f32x2 SGEMM (layers 1-2): C[M,128] = [dinv[row] *] (A[M,K] @ B[K,128])
// BM=128, BN=128, BK=16, TM=8, TN=8, 256 threads. (R10-proven structure.)
template <int K, bool SCALE>
__global__ void __launch_bounds__(256)
sgemm2(const float* __restrict__ Aext, int asel,
       const float* __restrict__ B, int csel, int M) {
    constexpr int BM = 128, BN = 128, BK = 16, TM = 8, TN = 8;
    constexpr int THREADS = 256;

    const float* A = (asel < 0) ? Aext : scratch_buf(asel);
    float* C = scratch_buf(csel);

    __shared__ __align__(16) float As[BK][BM + 2];
    __shared__ __align__(16) float Bs[BK][BN];

    const int block_row = blockIdx.y * BM;
    const int tid = threadIdx.x;
    const int tcol = tid % (BN / TN);   // 0..15
    const int trow = tid / (BN / TN);   // 0..15

    unsigned long long acc[TM][TN / 2];
#pragma unroll
    for (int i = 0; i < TM; i++)
#pragma unroll
        for (int j = 0; j < TN / 2; j++) acc[i][j] = 0ull;

    for (int k0 = 0; k0 < K; k0 += BK) {
        // Load A tile (BM x BK), transposed into As[k][m]
#pragma unroll
        for (int i = tid * 4; i < BM * BK; i += THREADS * 4) {
            int r = i / BK, c = i % BK;
            int row = block_row + r;
            float4 v = make_float4(0.f, 0.f, 0.f, 0.f);
            if (row < M) v = *(const float4*)(A + (size_t)row * K + k0 + c);
            As[c + 0][r] = v.x;
            As[c + 1][r] = v.y;
            As[c + 2][r] = v.z;
            As[c + 3][r] = v.w;
        }
        // Load B tile (BK x BN)
#pragma unroll
        for (int i = tid * 4; i < BK * BN; i += THREADS * 4) {
            int r = i / BN, c = i % BN;
            *(float4*)&Bs[r][c] = *(const float4*)(B + (size_t)(k0 + r) * BN + c);
        }
        __syncthreads();

#pragma unroll
        for (int k = 0; k < BK; k++) {
            unsigned long long a2[TM], b2[TN / 2];
#pragma unroll
            for (int i = 0; i < TM; i++) {
                float ra = As[k][trow * TM + i];
                PACK_DUP(a2[i], ra);
            }
#pragma unroll
            for (int j = 0; j < TN / 2; j++)
                b2[j] = *(const unsigned long long*)&Bs[k][tcol * TN + 2 * j];
#pragma unroll
            for (int i = 0; i < TM; i++)
#pragma unroll
                for (int j = 0; j < TN / 2; j++)
                    FMA_F32X2(acc[i][j], a2[i], b2[j]);
        }
        __syncthreads();
    }

    // Epilogue: optional dinv scale, store
#pragma unroll
    for (int i = 0; i < TM; i++) {
        int row = block_row + trow * TM + i;
        if (row < M) {
            float scale = SCALE ? g_dinv[row] : 1.0f;
            float* crow = C + (size_t)row * NH + tcol * TN;
#pragma unroll
            for (int j = 0; j < TN / 2; j += 2) {
                float4 v;
                UNPACK2(v.x, v.y, acc[i][j]);
                UNPACK2(v.z, v.w, acc[i][j + 1]);
                if (SCALE) { v.x *= scale; v.y *= scale; v.z *= scale; v.w *= scale; }
                *(float4*)(crow + 2 * j) = v;
            }
        }
    }
}

// ---------------- Tiled SGEMM (classifier, R10-proven) ----------------
template <int BM, int BN, int BK, int TM, int TN>
__global__ void sgemm(int asel, const float* __restrict__ B,
                      float* __restrict__ Cext,
                      const float* __restrict__ bias,
                      int M, int N, int K) {
    const float* A = scratch_buf(asel);
    float*       C = Cext;

    constexpr int THREADS = (BM / TM) * (BN / TN);
    __shared__ float As[BK][BM + 1];
    __shared__ float Bs[BK][BN];

    const int block_row = blockIdx.y * BM;
    const int tid = threadIdx.x;
    const int tcol = tid % (BN / TN);
    const int trow = tid / (BN / TN);

    float acc[TM][TN];
#pragma unroll
    for (int i = 0; i < TM; i++)
#pragma unroll
        for (int j = 0; j < TN; j++) acc[i][j] = 0.0f;

    for (int k0 = 0; k0 < K; k0 += BK) {
        for (int i = tid * 4; i < BM * BK; i += THREADS * 4) {
            int r = i / BK, c = i % BK;
            int row = block_row + r;
            float4 v = make_float4(0.f, 0.f, 0.f, 0.f);
            if (row < M) v = *(const float4*)(A + (size_t)row * K + k0 + c);
            As[c + 0][r] = v.x;
            As[c + 1][r] = v.y;
            As[c + 2][r] = v.z;
            As[c + 3][r] = v.w;
        }
        for (int i = tid * 4; i < BK * BN; i += THREADS * 4) {
            int r = i / BN, c = i % BN;
            *(float4*)&Bs[r][c] = *(const float4*)(B + (size_t)(k0 + r) * N + c);
        }
        __syncthreads();

#pragma unroll
        for (int k = 0; k < BK; k++) {
            float ra[TM], rb[TN];
#pragma unroll
            for (int i = 0; i < TM; i++) ra[i] = As[k][trow * TM + i];
#pragma unroll
            for (int j = 0; j < TN; j++) rb[j] = Bs[k][tcol * TN + j];
#pragma unroll
            for (int i = 0; i < TM; i++)
#pragma unroll
                for (int j = 0; j < TN; j++) acc[i][j] += ra[i] * rb[j];
        }
        __syncthreads();
    }

#pragma unroll
    for (int i = 0; i < TM; i++) {
        int row = block_row + trow * TM + i;
        if (row < M) {
#pragma unroll
            for (int j = 0; j < TN; j++) {
                int col = tcol * TN + j;
                C[(size_t)row * N + col] = acc[i][j] + bias[col];
            }
        }
    }
}

// ---------------- Fused aggregation: warp per node ----------------
// EDGE_DINV=0 (h pre-scaled): out = relu( dd*(h[i] + Σ h[s]) + b )
// EDGE_DINV=1 (h raw):        out = relu( dd*(dd*h[i] + Σ dinv[s]*h[s]) + b )
template <bool EDGE_DINV>
__global__ void k_aggregate(int hsel, const float* __restrict__ bias,
                            int osel, int n_nodes) {
    const float* __restrict__ h = scratch_buf(hsel);
    float* __restrict__ out = scratch_buf(osel);

    int warp = (blockIdx.x * blockDim.x + threadIdx.x) >> 5;
    if (warp >= n_nodes) return;
    int lane = threadIdx.x & 31;
    int node = warp;

    float dd = g_dinv[node];
    int start = g_off[node];
    int cnt = g_deg[node];

    const float* hb = h + (size_t)lane * 4;

    float4 acc = *(const float4*)(hb + (size_t)node * NH);
    if (EDGE_DINV) { acc.x *= dd; acc.y *= dd; acc.z *= dd; acc.w *= dd; }

    int j = 0;
    for (; j + 4 <= cnt; j += 4) {
        int s0 = g_csr[start + j + 0];
        int s1 = g_csr[start + j + 1];
        int s2 = g_csr[start + j + 2];
        int s3 = g_csr[start + j + 3];
        float4 v0 = *(const float4*)(hb + (size_t)s0 * NH);
        float4 v1 = *(const float4*)(hb + (size_t)s1 * NH);
        float4 v2 = *(const float4*)(hb + (size_t)s2 * NH);
        float4 v3 = *(const float4*)(hb + (size_t)s3 * NH);
        if (EDGE_DINV) {
            float w0 = g_dinv[s0], w1 = g_dinv[s1], w2 = g_dinv[s2], w3 = g_dinv[s3];
            acc.x = fmaf(v0.x, w0, fmaf(v1.x, w1, fmaf(v2.x, w2, fmaf(v3.x, w3, acc.x))));
            acc.y = fmaf(v0.y, w0, fmaf(v1.y, w1, fmaf(v2.y, w2, fmaf(v3.y, w3, acc.y))));
            acc.z = fmaf(v0.z, w0, fmaf(v1.z, w1, fmaf(v2.z, w2, fmaf(v3.z, w3, acc.z))));
            acc.w = fmaf(v0.w, w0, fmaf(v1.w, w1, fmaf(v2.w, w2, fmaf(v3.w, w3, acc.w))));
        } else {
            acc.x += (v0.x + v1.x) + (v2.x + v3.x);
            acc.y += (v0.y + v1.y) + (v2.y + v3.y);
            acc.z += (v0.z + v1.z) + (v2.z + v3.z);
            acc.w += (v0.w + v1.w) + (v2.w + v3.w);
        }
    }
    for (; j < cnt; j++) {
        int s = g_csr[start + j];
        float4 v = *(const float4*)(hb + (size_t)s * NH);
        if (EDGE_DINV) {
            float w = g_dinv[s];
            acc.x = fmaf(v.x, w, acc.x);
            acc.y = fmaf(v.y, w, acc.y);
            acc.z = fmaf(v.z, w, acc.z);
            acc.w = fmaf(v.w, w, acc.w);
        } else {
            acc.x += v.x; acc.y += v.y; acc.z += v.z; acc.w += v.w;
        }
    }

    int c = lane * 4;
    acc.x = fmaxf(fmaf(acc.x, dd, bias[c + 0]), 0.0f);
    acc.y = fmaxf(fmaf(acc.y, dd, bias[c + 1]), 0.0f);
    acc.z = fmaxf(fmaf(acc.z, dd, bias[c + 2]), 0.0f);
    acc.w = fmaxf(fmaf(acc.w, dd, bias[c + 3]), 0.0f);
    *(float4*)(out + (size_t)node * NH + c) = acc;
}

// ---------------- Launch ----------------
extern "C" void kernel_launch(void* const* d_in, const int* in_sizes, int n_in,
                              void* d_out, int out_size) {
    const float* x       = (const float*)d_in[0];
    const void*  ei      = d_in[1];
    const float* W1      = (const float*)d_in[2];
    const float* b1      = (const float*)d_in[3];
    const float* W2      = (const float*)d_in[4];
    const float* b2      = (const float*)d_in[5];
    const float* Wc      = (const float*)d_in[6];
    const float* bc      = (const float*)d_in[7];
    float* out           = (float*)d_out;

    const int N = in_sizes[0] / NF;       // 100000
    const int E = in_sizes[1] / 2;        // 1600000
    const int nb = (N + 1023) / 1024;

    // One-time side-stream + events (created on the uncaptured correctness
    // call; reused — and recorded as graph fork/join — on the capture call).
    static cudaStream_t s_side = nullptr;
    static cudaEvent_t  ev_fork = nullptr, ev_join = nullptr;
    if (s_side == nullptr) {
        cudaStreamCreateWithFlags(&s_side, cudaStreamNonBlocking);
        cudaEventCreateWithFlags(&ev_fork, cudaEventDisableTiming);
        cudaEventCreateWithFlags(&ev_join, cudaEventDisableTiming);
    }

    const int agg_blocks = (int)(((long long)N * 32 + 255) / 256);

    // ---- Fork: GEMM1 (no dinv dependence) runs concurrently with CSR build --
    cudaEventRecord(ev_fork, 0);
    cudaStreamWaitEvent(s_side, ev_fork, 0);
    {
        dim3 grid(1, (N + 127) / 128);
        sgemm2<NF, false><<<grid, 256, 0, s_side>>>(x, -1, W1, 0, N);
    }
    cudaEventRecord(ev_join, s_side);

    // ---- CSR build on the main stream (overlapped with GEMM1) ----
    k_detect_dtype<<<1, 256>>>((const long long*)ei);
    k_zero_deg<<<(N + 1023) / 1024, 1024>>>(N);
    k_count_deg<<<(E + 511) / 512, 512>>>(ei, E);
    k_scan_blocks<<<nb, 1024>>>(N);
    k_scan_sums<<<1, 128>>>(nb);
    k_scan_add<<<nb, 1024>>>(N);
    k_fill_csr<<<(E + 511) / 512, 512>>>(ei, E);

    // ---- Join: layer-1 aggregation needs both GEMM1 output and the CSR ----
    cudaStreamWaitEvent(0, ev_join, 0);
    k_aggregate<true><<<agg_blocks, 256>>>(0, b1, 1, N);

    // Layer 2: g_h1 = dinv * (g_ha @ W2) ; aggregate -> g_ha
    {
        dim3 grid(1, (N + 127) / 128);
        sgemm2<NH, true><<<grid, 256>>>(nullptr, 1, W2, 0, N);
    }
    k_aggregate<false><<<agg_blocks, 256>>>(0, b2, 1, N);

    // Classifier: out = g_ha @ Wc + bc
    {
        dim3 grid(1, (N + 127) / 128);
        sgemm<128, 40, 32, 4, 8><<<grid, 160>>>(1, Wc, out, bc, N, NC, NH);
    }
}